// round 13
// baseline (speedup 1.0000x reference)
#include <cuda_runtime.h>
#include <cuda_fp16.h>
#include <cstdint>

// SoftPixelRadiusCNN:
//   d      = sqrt(distsq + EPS)
//   w_i(k) = exp(-scaler * (d_k - i/ls)^2),  scaler = 10*ls*SUBDIV
//   out[v, i*F + f] = sum_k w_i(k) * features[nidx[v,k], f] / (sum_k w_i(k) + EPS)
// V=100000, K=32, F=64, SUBDIV=3.
//
// R13: 2-vertex ILP per warp on the fp16-gather half-warp layout.
// Evidence: SHFL cuts, gather-byte halving, and occupancy raises all failed to
// move ~80us; issue sits at 67-70% with no pipe saturated -> per-warp latency
// bubbles, and MORE WARPS made it worse (L1 queue contention). So fill the
// bubbles inside each warp: two independent vertex pipelines per warp.

#define K_NEIGH 32
#define F_DIM   64
#define SUBDIV  3
#define EPSV    1e-6f
#define OUT_F   (SUBDIV * F_DIM)
#define FULLM   0xFFFFFFFFu

#define V_CAP   100352                       // static fp16 buffer capacity (rows)
__device__ __half g_feat16[(size_t)V_CAP * F_DIM];   // 12.85 MB module-static scratch

// ---------------------------------------------------------------- convert
__global__ __launch_bounds__(256)
void convert_kernel(const float* __restrict__ features, int n4 /* V*F/4 */)
{
    const int stride = gridDim.x * blockDim.x;
    for (int i = blockIdx.x * blockDim.x + threadIdx.x; i < n4; i += stride) {
        const float4 x = reinterpret_cast<const float4*>(features)[i];
        __half2 lo = __floats2half2_rn(x.x, x.y);
        __half2 hi = __floats2half2_rn(x.z, x.w);
        const uint32_t lo_u = *reinterpret_cast<const uint32_t*>(&lo);
        const uint32_t hi_u = *reinterpret_cast<const uint32_t*>(&hi);
        reinterpret_cast<uint2*>(g_feat16)[i] = make_uint2(lo_u, hi_u);
    }
}

// ---------------------------------------------------------------- main (fp16 gather, 2-vertex ILP)
__global__ __launch_bounds__(256)
void softpixel_kernel_h(const float* __restrict__ distsq,
                        const int*   __restrict__ nidx,
                        const float* __restrict__ ls_ptr,
                        float*       __restrict__ out,
                        int V)
{
    const int lane   = threadIdx.x & 31;
    const int half   = lane >> 4;      // 0 or 1
    const int t      = lane & 15;      // 4-col group within the half
    const int warp0  = (blockIdx.x * blockDim.x + threadIdx.x) >> 5;
    const int nwarps = (gridDim.x * blockDim.x) >> 5;

    const float ls     = __ldg(ls_ptr);
    const float scaler = 10.0f * ls * (float)SUBDIV;
    const float inv_ls = 1.0f / ls;

    const __half* fbase = g_feat16 + (size_t)4 * t;

    for (int vA = warp0 * 2; vA < V; vA += nwarps * 2) {
        const int  vB   = vA + 1;
        const bool has2 = (vB < V);
        const int  vB_s = has2 ? vB : vA;            // safe source row

        // --- prologue: two vertices' per-lane neighbor data ---
        const float dsqA = __ldg(distsq + (size_t)vA  * K_NEIGH + lane);
        const float dsqB = __ldg(distsq + (size_t)vB_s * K_NEIGH + lane);
        const int   idxA = __ldg(nidx   + (size_t)vA  * K_NEIGH + lane);
        const int   idxB = __ldg(nidx   + (size_t)vB_s * K_NEIGH + lane);

        const float dA  = sqrtf(dsqA + EPSV);
        const float dB  = sqrtf(dsqB + EPSV);
        const float tA1 = dA - inv_ls,        tB1 = dB - inv_ls;
        const float tA2 = dA - 2.0f * inv_ls, tB2 = dB - 2.0f * inv_ls;
        const float wA0 = __expf(-scaler * dA  * dA),  wB0 = __expf(-scaler * dB  * dB);
        const float wA1 = __expf(-scaler * tA1 * tA1), wB1 = __expf(-scaler * tB1 * tB1);
        const float wA2 = __expf(-scaler * tA2 * tA2), wB2 = __expf(-scaler * tB2 * tB2);

        // --- two independent accumulator sets ---
        float4 aA0 = make_float4(0.f,0.f,0.f,0.f), aB0 = make_float4(0.f,0.f,0.f,0.f);
        float4 aA1 = make_float4(0.f,0.f,0.f,0.f), aB1 = make_float4(0.f,0.f,0.f,0.f);
        float4 aA2 = make_float4(0.f,0.f,0.f,0.f), aB2 = make_float4(0.f,0.f,0.f,0.f);
        float sA0 = 0.f, sA1 = 0.f, sA2 = 0.f;
        float sB0 = 0.f, sB1 = 0.f, sB2 = 0.f;

        int kj = half;
        #pragma unroll
        for (int j = 0; j < K_NEIGH / 2; ++j, kj += 2) {
            // stream A
            const int   ikA = __shfl_sync(FULLM, idxA, kj);
            const float bA0 = __shfl_sync(FULLM, wA0, kj);
            const float bA1 = __shfl_sync(FULLM, wA1, kj);
            const float bA2 = __shfl_sync(FULLM, wA2, kj);
            const uint2 pA  = *reinterpret_cast<const uint2*>(fbase + (size_t)ikA * F_DIM);
            // stream B (independent)
            const int   ikB = __shfl_sync(FULLM, idxB, kj);
            const float bB0 = __shfl_sync(FULLM, wB0, kj);
            const float bB1 = __shfl_sync(FULLM, wB1, kj);
            const float bB2 = __shfl_sync(FULLM, wB2, kj);
            const uint2 pB  = *reinterpret_cast<const uint2*>(fbase + (size_t)ikB * F_DIM);

            const float2 fAxy = __half22float2(*reinterpret_cast<const __half2*>(&pA.x));
            const float2 fAzw = __half22float2(*reinterpret_cast<const __half2*>(&pA.y));
            sA0 += bA0; sA1 += bA1; sA2 += bA2;
            aA0.x = fmaf(bA0, fAxy.x, aA0.x); aA0.y = fmaf(bA0, fAxy.y, aA0.y);
            aA0.z = fmaf(bA0, fAzw.x, aA0.z); aA0.w = fmaf(bA0, fAzw.y, aA0.w);
            aA1.x = fmaf(bA1, fAxy.x, aA1.x); aA1.y = fmaf(bA1, fAxy.y, aA1.y);
            aA1.z = fmaf(bA1, fAzw.x, aA1.z); aA1.w = fmaf(bA1, fAzw.y, aA1.w);
            aA2.x = fmaf(bA2, fAxy.x, aA2.x); aA2.y = fmaf(bA2, fAxy.y, aA2.y);
            aA2.z = fmaf(bA2, fAzw.x, aA2.z); aA2.w = fmaf(bA2, fAzw.y, aA2.w);

            const float2 fBxy = __half22float2(*reinterpret_cast<const __half2*>(&pB.x));
            const float2 fBzw = __half22float2(*reinterpret_cast<const __half2*>(&pB.y));
            sB0 += bB0; sB1 += bB1; sB2 += bB2;
            aB0.x = fmaf(bB0, fBxy.x, aB0.x); aB0.y = fmaf(bB0, fBxy.y, aB0.y);
            aB0.z = fmaf(bB0, fBzw.x, aB0.z); aB0.w = fmaf(bB0, fBzw.y, aB0.w);
            aB1.x = fmaf(bB1, fBxy.x, aB1.x); aB1.y = fmaf(bB1, fBxy.y, aB1.y);
            aB1.z = fmaf(bB1, fBzw.x, aB1.z); aB1.w = fmaf(bB1, fBzw.y, aB1.w);
            aB2.x = fmaf(bB2, fBxy.x, aB2.x); aB2.y = fmaf(bB2, fBxy.y, aB2.y);
            aB2.z = fmaf(bB2, fBzw.x, aB2.z); aB2.w = fmaf(bB2, fBzw.y, aB2.w);
        }

        // --- combine even/odd halves for both vertices ---
        aA0.x += __shfl_xor_sync(FULLM, aA0.x, 16); aA0.y += __shfl_xor_sync(FULLM, aA0.y, 16);
        aA0.z += __shfl_xor_sync(FULLM, aA0.z, 16); aA0.w += __shfl_xor_sync(FULLM, aA0.w, 16);
        aA1.x += __shfl_xor_sync(FULLM, aA1.x, 16); aA1.y += __shfl_xor_sync(FULLM, aA1.y, 16);
        aA1.z += __shfl_xor_sync(FULLM, aA1.z, 16); aA1.w += __shfl_xor_sync(FULLM, aA1.w, 16);
        aA2.x += __shfl_xor_sync(FULLM, aA2.x, 16); aA2.y += __shfl_xor_sync(FULLM, aA2.y, 16);
        aA2.z += __shfl_xor_sync(FULLM, aA2.z, 16); aA2.w += __shfl_xor_sync(FULLM, aA2.w, 16);
        sA0   += __shfl_xor_sync(FULLM, sA0,   16);
        sA1   += __shfl_xor_sync(FULLM, sA1,   16);
        sA2   += __shfl_xor_sync(FULLM, sA2,   16);

        aB0.x += __shfl_xor_sync(FULLM, aB0.x, 16); aB0.y += __shfl_xor_sync(FULLM, aB0.y, 16);
        aB0.z += __shfl_xor_sync(FULLM, aB0.z, 16); aB0.w += __shfl_xor_sync(FULLM, aB0.w, 16);
        aB1.x += __shfl_xor_sync(FULLM, aB1.x, 16); aB1.y += __shfl_xor_sync(FULLM, aB1.y, 16);
        aB1.z += __shfl_xor_sync(FULLM, aB1.z, 16); aB1.w += __shfl_xor_sync(FULLM, aB1.w, 16);
        aB2.x += __shfl_xor_sync(FULLM, aB2.x, 16); aB2.y += __shfl_xor_sync(FULLM, aB2.y, 16);
        aB2.z += __shfl_xor_sync(FULLM, aB2.z, 16); aB2.w += __shfl_xor_sync(FULLM, aB2.w, 16);
        sB0   += __shfl_xor_sync(FULLM, sB0,   16);
        sB1   += __shfl_xor_sync(FULLM, sB1,   16);
        sB2   += __shfl_xor_sync(FULLM, sB2,   16);

        // --- stores: half 0 -> bins 0,2; half 1 -> bin 1 ---
        {
            float* obase = out + (size_t)vA * OUT_F + 4 * t;
            if (half == 0) {
                const float r0 = 1.0f / (sA0 + EPSV);
                const float r2 = 1.0f / (sA2 + EPSV);
                *reinterpret_cast<float4*>(obase) =
                    make_float4(aA0.x * r0, aA0.y * r0, aA0.z * r0, aA0.w * r0);
                *reinterpret_cast<float4*>(obase + 2 * F_DIM) =
                    make_float4(aA2.x * r2, aA2.y * r2, aA2.z * r2, aA2.w * r2);
            } else {
                const float r1 = 1.0f / (sA1 + EPSV);
                *reinterpret_cast<float4*>(obase + F_DIM) =
                    make_float4(aA1.x * r1, aA1.y * r1, aA1.z * r1, aA1.w * r1);
            }
        }
        if (has2) {
            float* obase = out + (size_t)vB * OUT_F + 4 * t;
            if (half == 0) {
                const float r0 = 1.0f / (sB0 + EPSV);
                const float r2 = 1.0f / (sB2 + EPSV);
                *reinterpret_cast<float4*>(obase) =
                    make_float4(aB0.x * r0, aB0.y * r0, aB0.z * r0, aB0.w * r0);
                *reinterpret_cast<float4*>(obase + 2 * F_DIM) =
                    make_float4(aB2.x * r2, aB2.y * r2, aB2.z * r2, aB2.w * r2);
            } else {
                const float r1 = 1.0f / (sB1 + EPSV);
                *reinterpret_cast<float4*>(obase + F_DIM) =
                    make_float4(aB1.x * r1, aB1.y * r1, aB1.z * r1, aB1.w * r1);
            }
        }
    }
}

// ---------------------------------------------------------------- fallback (fp32 gather)
__global__ __launch_bounds__(256)
void softpixel_kernel_f(const float* __restrict__ features,
                        const float* __restrict__ distsq,
                        const int*   __restrict__ nidx,
                        const float* __restrict__ ls_ptr,
                        float*       __restrict__ out,
                        int V)
{
    const int lane   = threadIdx.x & 31;
    const int half   = lane >> 4;
    const int t      = lane & 15;
    const int warp0  = (blockIdx.x * blockDim.x + threadIdx.x) >> 5;
    const int nwarps = (gridDim.x * blockDim.x) >> 5;

    const float ls     = __ldg(ls_ptr);
    const float scaler = 10.0f * ls * (float)SUBDIV;
    const float inv_ls = 1.0f / ls;

    for (int v = warp0; v < V; v += nwarps) {
        const float dsq    = __ldg(distsq + (size_t)v * K_NEIGH + lane);
        const int   my_idx = __ldg(nidx   + (size_t)v * K_NEIGH + lane);
        const float d  = sqrtf(dsq + EPSV);
        const float t1 = d - inv_ls;
        const float t2 = d - 2.0f * inv_ls;
        const float w0 = __expf(-scaler * d  * d);
        const float w1 = __expf(-scaler * t1 * t1);
        const float w2 = __expf(-scaler * t2 * t2);

        float4 a0 = make_float4(0.f, 0.f, 0.f, 0.f);
        float4 a1 = make_float4(0.f, 0.f, 0.f, 0.f);
        float4 a2 = make_float4(0.f, 0.f, 0.f, 0.f);
        float s0 = 0.f, s1 = 0.f, s2 = 0.f;
        const float* fbase = features + (size_t)4 * t;

        int kj = half;
        #pragma unroll
        for (int j = 0; j < K_NEIGH / 2; ++j, kj += 2) {
            const int   ik = __shfl_sync(FULLM, my_idx, kj);
            const float b0 = __shfl_sync(FULLM, w0, kj);
            const float b1 = __shfl_sync(FULLM, w1, kj);
            const float b2 = __shfl_sync(FULLM, w2, kj);
            const float4 f = *reinterpret_cast<const float4*>(fbase + (size_t)ik * F_DIM);
            s0 += b0; s1 += b1; s2 += b2;
            a0.x = fmaf(b0, f.x, a0.x); a0.y = fmaf(b0, f.y, a0.y);
            a0.z = fmaf(b0, f.z, a0.z); a0.w = fmaf(b0, f.w, a0.w);
            a1.x = fmaf(b1, f.x, a1.x); a1.y = fmaf(b1, f.y, a1.y);
            a1.z = fmaf(b1, f.z, a1.z); a1.w = fmaf(b1, f.w, a1.w);
            a2.x = fmaf(b2, f.x, a2.x); a2.y = fmaf(b2, f.y, a2.y);
            a2.z = fmaf(b2, f.z, a2.z); a2.w = fmaf(b2, f.w, a2.w);
        }

        a0.x += __shfl_xor_sync(FULLM, a0.x, 16); a0.y += __shfl_xor_sync(FULLM, a0.y, 16);
        a0.z += __shfl_xor_sync(FULLM, a0.z, 16); a0.w += __shfl_xor_sync(FULLM, a0.w, 16);
        a1.x += __shfl_xor_sync(FULLM, a1.x, 16); a1.y += __shfl_xor_sync(FULLM, a1.y, 16);
        a1.z += __shfl_xor_sync(FULLM, a1.z, 16); a1.w += __shfl_xor_sync(FULLM, a1.w, 16);
        a2.x += __shfl_xor_sync(FULLM, a2.x, 16); a2.y += __shfl_xor_sync(FULLM, a2.y, 16);
        a2.z += __shfl_xor_sync(FULLM, a2.z, 16); a2.w += __shfl_xor_sync(FULLM, a2.w, 16);
        s0   += __shfl_xor_sync(FULLM, s0,   16);
        s1   += __shfl_xor_sync(FULLM, s1,   16);
        s2   += __shfl_xor_sync(FULLM, s2,   16);

        float* obase = out + (size_t)v * OUT_F + 4 * t;
        if (half == 0) {
            const float r0 = 1.0f / (s0 + EPSV);
            const float r2 = 1.0f / (s2 + EPSV);
            *reinterpret_cast<float4*>(obase) =
                make_float4(a0.x * r0, a0.y * r0, a0.z * r0, a0.w * r0);
            *reinterpret_cast<float4*>(obase + 2 * F_DIM) =
                make_float4(a2.x * r2, a2.y * r2, a2.z * r2, a2.w * r2);
        } else {
            const float r1 = 1.0f / (s1 + EPSV);
            *reinterpret_cast<float4*>(obase + F_DIM) =
                make_float4(a1.x * r1, a1.y * r1, a1.z * r1, a1.w * r1);
        }
    }
}

extern "C" void kernel_launch(void* const* d_in, const int* in_sizes, int n_in,
                              void* d_out, int out_size)
{
    const float* features = (const float*)d_in[0];
    const float* distsq   = (const float*)d_in[1];
    const int*   nidx     = (const int*)  d_in[2];
    const float* ls       = (const float*)d_in[3];
    float*       out      = (float*)d_out;

    int V = out_size / OUT_F;
    if (V <= 0) V = in_sizes[1] / K_NEIGH;

    const int threads = 256;

    if (V <= V_CAP) {
        const int n4 = (V * F_DIM) / 4;               // float4 count
        int cblocks = (n4 + threads - 1) / threads;
        if (cblocks > 4096) cblocks = 4096;
        if (cblocks < 1) cblocks = 1;
        convert_kernel<<<cblocks, threads>>>(features, n4);

        // one warp per 2 vertices
        const int vpairs = (V + 1) / 2;
        int blocks = (vpairs * 32 + threads - 1) / threads;
        if (blocks < 1) blocks = 1;
        softpixel_kernel_h<<<blocks, threads>>>(distsq, nidx, ls, out, V);
    } else {
        int blocks = (V * 32 + threads - 1) / threads;
        if (blocks < 1) blocks = 1;
        softpixel_kernel_f<<<blocks, threads>>>(features, distsq, nidx, ls, out, V);
    }
}

// round 14
// speedup vs baseline: 1.0163x; 1.0163x over previous
#include <cuda_runtime.h>
#include <cuda_fp16.h>
#include <cstdint>

// SoftPixelRadiusCNN:
//   d      = sqrt(distsq + EPS)
//   w_i(k) = exp(-scaler * (d_k - i/ls)^2),  scaler = 10*ls*SUBDIV
//   out[v, i*F + f] = sum_k w_i(k) * features[nidx[v,k], f] / (sum_k w_i(k) + EPS)
// V=100000, K=32, F=64, SUBDIV=3.
//
// R14: fp16-compressed gather (kills the fp32 L2-bandwidth wall: 819MB ->
// 410MB) + packed fma.rn.f32x2 accumulation (halves the FMA-pipe instruction
// floor 45us -> 24us, exact fp32 math). One warp/vertex, half-warp rows,
// 2 neighbors per iteration, in-loop packed denominators (no butterfly).

#define K_NEIGH 32
#define F_DIM   64
#define SUBDIV  3
#define EPSV    1e-6f
#define OUT_F   (SUBDIV * F_DIM)
#define FULLM   0xFFFFFFFFu

#define V_CAP   100352                       // static fp16 buffer capacity (rows)
__device__ __half g_feat16[(size_t)V_CAP * F_DIM];   // 12.85 MB module-static scratch

// ---- packed f32x2 helpers (Blackwell) ----
__device__ __forceinline__ unsigned long long h2_to_f32x2(uint32_t h2) {
    unsigned long long r;
    asm("{\n\t"
        ".reg .b16 h0, h1;\n\t"
        ".reg .f32 f0, f1;\n\t"
        "mov.b32 {h0, h1}, %1;\n\t"
        "cvt.f32.f16 f0, h0;\n\t"
        "cvt.f32.f16 f1, h1;\n\t"
        "mov.b64 %0, {f0, f1};\n\t"
        "}" : "=l"(r) : "r"(h2));
    return r;
}
__device__ __forceinline__ unsigned long long pack_ff(float a, float b) {
    unsigned long long r;
    asm("mov.b64 %0, {%1, %2};" : "=l"(r) : "f"(a), "f"(b));
    return r;
}
__device__ __forceinline__ void ffma2(unsigned long long& acc,
                                      unsigned long long m, unsigned long long v) {
    asm("fma.rn.f32x2 %0, %1, %2, %0;" : "+l"(acc) : "l"(m), "l"(v));
}
__device__ __forceinline__ void fadd2(unsigned long long& acc, unsigned long long v) {
    asm("add.rn.f32x2 %0, %0, %1;" : "+l"(acc) : "l"(v));
}
__device__ __forceinline__ float2 unpack_f2(unsigned long long p) {
    float2 r;
    asm("mov.b64 {%0, %1}, %2;" : "=f"(r.x), "=f"(r.y) : "l"(p));
    return r;
}

// ---------------------------------------------------------------- convert
__global__ __launch_bounds__(256)
void convert_kernel(const float* __restrict__ features, int n4 /* V*F/4 */)
{
    const int stride = gridDim.x * blockDim.x;
    for (int i = blockIdx.x * blockDim.x + threadIdx.x; i < n4; i += stride) {
        const float4 x = reinterpret_cast<const float4*>(features)[i];
        __half2 lo = __floats2half2_rn(x.x, x.y);
        __half2 hi = __floats2half2_rn(x.z, x.w);
        const uint32_t lo_u = *reinterpret_cast<const uint32_t*>(&lo);
        const uint32_t hi_u = *reinterpret_cast<const uint32_t*>(&hi);
        reinterpret_cast<uint2*>(g_feat16)[i] = make_uint2(lo_u, hi_u);
    }
}

// ---------------------------------------------------------------- main (fp16 gather, f32x2 math)
__global__ __launch_bounds__(256)
void softpixel_kernel_h(const float* __restrict__ distsq,
                        const int*   __restrict__ nidx,
                        const float* __restrict__ ls_ptr,
                        float*       __restrict__ out,
                        int V)
{
    const int lane   = threadIdx.x & 31;
    const int half   = lane >> 4;      // 0 or 1
    const int t      = lane & 15;      // 4-col group within the half
    const int warp0  = (blockIdx.x * blockDim.x + threadIdx.x) >> 5;
    const int nwarps = (gridDim.x * blockDim.x) >> 5;

    const float ls     = __ldg(ls_ptr);
    const float scaler = 10.0f * ls * (float)SUBDIV;
    const float inv_ls = 1.0f / ls;

    const __half* fbase = g_feat16 + (size_t)4 * t;

    for (int v = warp0; v < V; v += nwarps) {
        // --- per-lane neighbor (k = lane): distance, index, 3 bin weights ---
        const float dsq    = __ldg(distsq + (size_t)v * K_NEIGH + lane);
        const int   my_idx = __ldg(nidx   + (size_t)v * K_NEIGH + lane);
        const float d  = sqrtf(dsq + EPSV);
        const float t1 = d - inv_ls;
        const float t2 = d - 2.0f * inv_ls;
        const float w0 = __expf(-scaler * d  * d);
        const float w1 = __expf(-scaler * t1 * t1);
        const float w2 = __expf(-scaler * t2 * t2);

        // --- packed accumulators: bin i covers cols (4t..4t+1) and (4t+2..4t+3) ---
        unsigned long long A0a = 0ull, A0b = 0ull;
        unsigned long long A1a = 0ull, A1b = 0ull;
        unsigned long long A2a = 0ull, A2b = 0ull;
        unsigned long long S01 = 0ull;           // packed (sum w0, sum w1)
        float s2 = 0.f;

        int kj = half;                     // this half's neighbors: half, half+2, ...
        #pragma unroll
        for (int j = 0; j < K_NEIGH / 2; ++j, kj += 2) {
            const int   ik = __shfl_sync(FULLM, my_idx, kj);
            const float b0 = __shfl_sync(FULLM, w0, kj);
            const float b1 = __shfl_sync(FULLM, w1, kj);
            const float b2 = __shfl_sync(FULLM, w2, kj);
            const uint2 p  = *reinterpret_cast<const uint2*>(fbase + (size_t)ik * F_DIM);
            const unsigned long long F01 = h2_to_f32x2(p.x);
            const unsigned long long F23 = h2_to_f32x2(p.y);
            const unsigned long long B0  = pack_ff(b0, b0);
            const unsigned long long B1  = pack_ff(b1, b1);
            const unsigned long long B2  = pack_ff(b2, b2);
            ffma2(A0a, B0, F01); ffma2(A0b, B0, F23);
            ffma2(A1a, B1, F01); ffma2(A1b, B1, F23);
            ffma2(A2a, B2, F01); ffma2(A2b, B2, F23);
            fadd2(S01, pack_ff(b0, b1));
            s2 += b2;
        }

        // --- unpack and combine even-k / odd-k halves (15 SHFLs) ---
        float2 a0xy = unpack_f2(A0a), a0zw = unpack_f2(A0b);
        float2 a1xy = unpack_f2(A1a), a1zw = unpack_f2(A1b);
        float2 a2xy = unpack_f2(A2a), a2zw = unpack_f2(A2b);
        float2 s01  = unpack_f2(S01);

        a0xy.x += __shfl_xor_sync(FULLM, a0xy.x, 16); a0xy.y += __shfl_xor_sync(FULLM, a0xy.y, 16);
        a0zw.x += __shfl_xor_sync(FULLM, a0zw.x, 16); a0zw.y += __shfl_xor_sync(FULLM, a0zw.y, 16);
        a1xy.x += __shfl_xor_sync(FULLM, a1xy.x, 16); a1xy.y += __shfl_xor_sync(FULLM, a1xy.y, 16);
        a1zw.x += __shfl_xor_sync(FULLM, a1zw.x, 16); a1zw.y += __shfl_xor_sync(FULLM, a1zw.y, 16);
        a2xy.x += __shfl_xor_sync(FULLM, a2xy.x, 16); a2xy.y += __shfl_xor_sync(FULLM, a2xy.y, 16);
        a2zw.x += __shfl_xor_sync(FULLM, a2zw.x, 16); a2zw.y += __shfl_xor_sync(FULLM, a2zw.y, 16);
        s01.x   += __shfl_xor_sync(FULLM, s01.x,   16);
        s01.y   += __shfl_xor_sync(FULLM, s01.y,   16);
        s2      += __shfl_xor_sync(FULLM, s2,      16);

        // --- write (V, 3*F): half 0 -> bins 0,2; half 1 -> bin 1 ---
        float* obase = out + (size_t)v * OUT_F + 4 * t;
        if (half == 0) {
            const float r0 = 1.0f / (s01.x + EPSV);
            const float r2 = 1.0f / (s2    + EPSV);
            *reinterpret_cast<float4*>(obase) =
                make_float4(a0xy.x * r0, a0xy.y * r0, a0zw.x * r0, a0zw.y * r0);
            *reinterpret_cast<float4*>(obase + 2 * F_DIM) =
                make_float4(a2xy.x * r2, a2xy.y * r2, a2zw.x * r2, a2zw.y * r2);
        } else {
            const float r1 = 1.0f / (s01.y + EPSV);
            *reinterpret_cast<float4*>(obase + F_DIM) =
                make_float4(a1xy.x * r1, a1xy.y * r1, a1zw.x * r1, a1zw.y * r1);
        }
    }
}

// ---------------------------------------------------------------- fallback (fp32 gather)
__global__ __launch_bounds__(256)
void softpixel_kernel_f(const float* __restrict__ features,
                        const float* __restrict__ distsq,
                        const int*   __restrict__ nidx,
                        const float* __restrict__ ls_ptr,
                        float*       __restrict__ out,
                        int V)
{
    const int lane   = threadIdx.x & 31;
    const int half   = lane >> 4;
    const int t      = lane & 15;
    const int warp0  = (blockIdx.x * blockDim.x + threadIdx.x) >> 5;
    const int nwarps = (gridDim.x * blockDim.x) >> 5;

    const float ls     = __ldg(ls_ptr);
    const float scaler = 10.0f * ls * (float)SUBDIV;
    const float inv_ls = 1.0f / ls;

    for (int v = warp0; v < V; v += nwarps) {
        const float dsq    = __ldg(distsq + (size_t)v * K_NEIGH + lane);
        const int   my_idx = __ldg(nidx   + (size_t)v * K_NEIGH + lane);
        const float d  = sqrtf(dsq + EPSV);
        const float t1 = d - inv_ls;
        const float t2 = d - 2.0f * inv_ls;
        const float w0 = __expf(-scaler * d  * d);
        const float w1 = __expf(-scaler * t1 * t1);
        const float w2 = __expf(-scaler * t2 * t2);

        float4 a0 = make_float4(0.f, 0.f, 0.f, 0.f);
        float4 a1 = make_float4(0.f, 0.f, 0.f, 0.f);
        float4 a2 = make_float4(0.f, 0.f, 0.f, 0.f);
        float s0 = 0.f, s1 = 0.f, s2 = 0.f;
        const float* fbase = features + (size_t)4 * t;

        int kj = half;
        #pragma unroll
        for (int j = 0; j < K_NEIGH / 2; ++j, kj += 2) {
            const int   ik = __shfl_sync(FULLM, my_idx, kj);
            const float b0 = __shfl_sync(FULLM, w0, kj);
            const float b1 = __shfl_sync(FULLM, w1, kj);
            const float b2 = __shfl_sync(FULLM, w2, kj);
            const float4 f = *reinterpret_cast<const float4*>(fbase + (size_t)ik * F_DIM);
            s0 += b0; s1 += b1; s2 += b2;
            a0.x = fmaf(b0, f.x, a0.x); a0.y = fmaf(b0, f.y, a0.y);
            a0.z = fmaf(b0, f.z, a0.z); a0.w = fmaf(b0, f.w, a0.w);
            a1.x = fmaf(b1, f.x, a1.x); a1.y = fmaf(b1, f.y, a1.y);
            a1.z = fmaf(b1, f.z, a1.z); a1.w = fmaf(b1, f.w, a1.w);
            a2.x = fmaf(b2, f.x, a2.x); a2.y = fmaf(b2, f.y, a2.y);
            a2.z = fmaf(b2, f.z, a2.z); a2.w = fmaf(b2, f.w, a2.w);
        }

        a0.x += __shfl_xor_sync(FULLM, a0.x, 16); a0.y += __shfl_xor_sync(FULLM, a0.y, 16);
        a0.z += __shfl_xor_sync(FULLM, a0.z, 16); a0.w += __shfl_xor_sync(FULLM, a0.w, 16);
        a1.x += __shfl_xor_sync(FULLM, a1.x, 16); a1.y += __shfl_xor_sync(FULLM, a1.y, 16);
        a1.z += __shfl_xor_sync(FULLM, a1.z, 16); a1.w += __shfl_xor_sync(FULLM, a1.w, 16);
        a2.x += __shfl_xor_sync(FULLM, a2.x, 16); a2.y += __shfl_xor_sync(FULLM, a2.y, 16);
        a2.z += __shfl_xor_sync(FULLM, a2.z, 16); a2.w += __shfl_xor_sync(FULLM, a2.w, 16);
        s0   += __shfl_xor_sync(FULLM, s0,   16);
        s1   += __shfl_xor_sync(FULLM, s1,   16);
        s2   += __shfl_xor_sync(FULLM, s2,   16);

        float* obase = out + (size_t)v * OUT_F + 4 * t;
        if (half == 0) {
            const float r0 = 1.0f / (s0 + EPSV);
            const float r2 = 1.0f / (s2 + EPSV);
            *reinterpret_cast<float4*>(obase) =
                make_float4(a0.x * r0, a0.y * r0, a0.z * r0, a0.w * r0);
            *reinterpret_cast<float4*>(obase + 2 * F_DIM) =
                make_float4(a2.x * r2, a2.y * r2, a2.z * r2, a2.w * r2);
        } else {
            const float r1 = 1.0f / (s1 + EPSV);
            *reinterpret_cast<float4*>(obase + F_DIM) =
                make_float4(a1.x * r1, a1.y * r1, a1.z * r1, a1.w * r1);
        }
    }
}

extern "C" void kernel_launch(void* const* d_in, const int* in_sizes, int n_in,
                              void* d_out, int out_size)
{
    const float* features = (const float*)d_in[0];
    const float* distsq   = (const float*)d_in[1];
    const int*   nidx     = (const int*)  d_in[2];
    const float* ls       = (const float*)d_in[3];
    float*       out      = (float*)d_out;

    int V = out_size / OUT_F;
    if (V <= 0) V = in_sizes[1] / K_NEIGH;

    const int threads = 256;
    int blocks = (V * 32 + threads - 1) / threads;
    if (blocks < 1) blocks = 1;

    if (V <= V_CAP) {
        const int n4 = (V * F_DIM) / 4;               // float4 count
        int cblocks = (n4 + threads - 1) / threads;
        if (cblocks > 4096) cblocks = 4096;
        if (cblocks < 1) cblocks = 1;
        convert_kernel<<<cblocks, threads>>>(features, n4);
        softpixel_kernel_h<<<blocks, threads>>>(distsq, nidx, ls, out, V);
    } else {
        softpixel_kernel_f<<<blocks, threads>>>(features, distsq, nidx, ls, out, V);
    }
}

// round 15
// speedup vs baseline: 1.1407x; 1.1224x over previous
#include <cuda_runtime.h>
#include <cuda_fp16.h>
#include <cstdint>

// SoftPixelRadiusCNN:
//   d      = sqrt(distsq + EPS)
//   w_i(k) = exp(-scaler * (d_k - i/ls)^2),  scaler = 10*ls*SUBDIV
//   out[v, i*F + f] = sum_k w_i(k) * features[nidx[v,k], f] / (sum_k w_i(k) + EPS)
// V=100000, K=32, F=64, SUBDIV=3.
//
// R15: HFMA2 datapath. The kernel is total-issue bound (~543 warp-instrs/vertex
// in R5); HFMA2 does 2 MACs/instr at FFMA rate and consumes the fp16 gathered
// data with ZERO converts. Loop = 3 SHFL + 1 LDG + 2 PRMT + 6 HFMA2 (~14/iter
// vs 22). fp16 chains drained to fp32 every 8 iters; weights packed as half2
// once per lane; denominators exact fp32 butterfly.

#define K_NEIGH 32
#define F_DIM   64
#define SUBDIV  3
#define EPSV    1e-6f
#define OUT_F   (SUBDIV * F_DIM)
#define FULLM   0xFFFFFFFFu

#define V_CAP   100352                       // static fp16 buffer capacity (rows)
__device__ __half g_feat16[(size_t)V_CAP * F_DIM];   // 12.85 MB module-static scratch

__device__ __forceinline__ __half2 u32_as_h2(uint32_t u) {
    __half2 h;
    *reinterpret_cast<uint32_t*>(&h) = u;
    return h;
}
__device__ __forceinline__ uint32_t h2_as_u32(__half2 h) {
    return *reinterpret_cast<uint32_t*>(&h);
}

// ---------------------------------------------------------------- convert
__global__ __launch_bounds__(256)
void convert_kernel(const float* __restrict__ features, int n4 /* V*F/4 */)
{
    const int stride = gridDim.x * blockDim.x;
    for (int i = blockIdx.x * blockDim.x + threadIdx.x; i < n4; i += stride) {
        const float4 x = reinterpret_cast<const float4*>(features)[i];
        __half2 lo = __floats2half2_rn(x.x, x.y);
        __half2 hi = __floats2half2_rn(x.z, x.w);
        reinterpret_cast<uint2*>(g_feat16)[i] = make_uint2(h2_as_u32(lo), h2_as_u32(hi));
    }
}

// ---------------------------------------------------------------- main (fp16 gather + HFMA2)
__global__ __launch_bounds__(256)
void softpixel_kernel_h(const float* __restrict__ distsq,
                        const int*   __restrict__ nidx,
                        const float* __restrict__ ls_ptr,
                        float*       __restrict__ out,
                        int V)
{
    const int lane   = threadIdx.x & 31;
    const int half_  = lane >> 4;      // 0 or 1
    const int t      = lane & 15;      // 4-col group within the half
    const int warp0  = (blockIdx.x * blockDim.x + threadIdx.x) >> 5;
    const int nwarps = (gridDim.x * blockDim.x) >> 5;

    const float ls     = __ldg(ls_ptr);
    const float scaler = 10.0f * ls * (float)SUBDIV;
    const float inv_ls = 1.0f / ls;

    const __half* fbase = g_feat16 + (size_t)4 * t;

    for (int v = warp0; v < V; v += nwarps) {
        // --- per-lane neighbor (k = lane): distance, index, 3 bin weights ---
        const float dsq    = __ldg(distsq + (size_t)v * K_NEIGH + lane);
        const int   my_idx = __ldg(nidx   + (size_t)v * K_NEIGH + lane);
        const float d  = sqrtf(dsq + EPSV);
        const float t1 = d - inv_ls;
        const float t2 = d - 2.0f * inv_ls;
        const float w0 = __expf(-scaler * d  * d);
        const float w1 = __expf(-scaler * t1 * t1);
        const float w2 = __expf(-scaler * t2 * t2);

        // pre-pack this lane's weights for broadcast: (w0,w1) and (w2,w2)
        const uint32_t u01 = h2_as_u32(__floats2half2_rn(w0, w1));
        const uint32_t u22 = h2_as_u32(__floats2half2_rn(w2, w2));

        // --- exact fp32 denominators: 15-SHFL butterfly (all lanes full) ---
        float s0 = w0, s1 = w1, s2 = w2;
        #pragma unroll
        for (int off = 16; off > 0; off >>= 1) {
            s0 += __shfl_xor_sync(FULLM, s0, off);
            s1 += __shfl_xor_sync(FULLM, s1, off);
            s2 += __shfl_xor_sync(FULLM, s2, off);
        }

        // --- fp16 accumulators (drained to fp32 every 8 iterations) ---
        __half2 c0a = u32_as_h2(0), c0b = u32_as_h2(0);
        __half2 c1a = u32_as_h2(0), c1b = u32_as_h2(0);
        __half2 c2a = u32_as_h2(0), c2b = u32_as_h2(0);
        float2 A0a = make_float2(0.f,0.f), A0b = make_float2(0.f,0.f);
        float2 A1a = make_float2(0.f,0.f), A1b = make_float2(0.f,0.f);
        float2 A2a = make_float2(0.f,0.f), A2b = make_float2(0.f,0.f);

        int kj = half_;                    // this half's neighbors: half, half+2, ...
        #pragma unroll
        for (int j = 0; j < K_NEIGH / 2; ++j, kj += 2) {
            const int      ik  = __shfl_sync(FULLM, my_idx, kj);
            const uint32_t p01 = __shfl_sync(FULLM, u01, kj);
            const uint32_t p22 = __shfl_sync(FULLM, u22, kj);
            const uint2 p = *reinterpret_cast<const uint2*>(fbase + (size_t)ik * F_DIM);
            const __half2 fx = u32_as_h2(p.x);       // cols 4t,4t+1
            const __half2 fy = u32_as_h2(p.y);       // cols 4t+2,4t+3
            const __half2 b00 = u32_as_h2(__byte_perm(p01, p01, 0x1010)); // (w0,w0)
            const __half2 b11 = u32_as_h2(__byte_perm(p01, p01, 0x3232)); // (w1,w1)
            const __half2 b22 = u32_as_h2(p22);                            // (w2,w2)
            c0a = __hfma2(b00, fx, c0a);  c0b = __hfma2(b00, fy, c0b);
            c1a = __hfma2(b11, fx, c1a);  c1b = __hfma2(b11, fy, c1b);
            c2a = __hfma2(b22, fx, c2a);  c2b = __hfma2(b22, fy, c2b);

            if (j == 7) {   // mid drain: keep fp16 chains at length 8
                float2 f2;
                f2 = __half22float2(c0a); A0a.x += f2.x; A0a.y += f2.y;
                f2 = __half22float2(c0b); A0b.x += f2.x; A0b.y += f2.y;
                f2 = __half22float2(c1a); A1a.x += f2.x; A1a.y += f2.y;
                f2 = __half22float2(c1b); A1b.x += f2.x; A1b.y += f2.y;
                f2 = __half22float2(c2a); A2a.x += f2.x; A2a.y += f2.y;
                f2 = __half22float2(c2b); A2b.x += f2.x; A2b.y += f2.y;
                c0a = u32_as_h2(0); c0b = u32_as_h2(0);
                c1a = u32_as_h2(0); c1b = u32_as_h2(0);
                c2a = u32_as_h2(0); c2b = u32_as_h2(0);
            }
        }
        {   // final drain
            float2 f2;
            f2 = __half22float2(c0a); A0a.x += f2.x; A0a.y += f2.y;
            f2 = __half22float2(c0b); A0b.x += f2.x; A0b.y += f2.y;
            f2 = __half22float2(c1a); A1a.x += f2.x; A1a.y += f2.y;
            f2 = __half22float2(c1b); A1b.x += f2.x; A1b.y += f2.y;
            f2 = __half22float2(c2a); A2a.x += f2.x; A2a.y += f2.y;
            f2 = __half22float2(c2b); A2b.x += f2.x; A2b.y += f2.y;
        }

        // --- combine even-k (half 0) / odd-k (half 1) partials: 12 SHFLs ---
        A0a.x += __shfl_xor_sync(FULLM, A0a.x, 16); A0a.y += __shfl_xor_sync(FULLM, A0a.y, 16);
        A0b.x += __shfl_xor_sync(FULLM, A0b.x, 16); A0b.y += __shfl_xor_sync(FULLM, A0b.y, 16);
        A1a.x += __shfl_xor_sync(FULLM, A1a.x, 16); A1a.y += __shfl_xor_sync(FULLM, A1a.y, 16);
        A1b.x += __shfl_xor_sync(FULLM, A1b.x, 16); A1b.y += __shfl_xor_sync(FULLM, A1b.y, 16);
        A2a.x += __shfl_xor_sync(FULLM, A2a.x, 16); A2a.y += __shfl_xor_sync(FULLM, A2a.y, 16);
        A2b.x += __shfl_xor_sync(FULLM, A2b.x, 16); A2b.y += __shfl_xor_sync(FULLM, A2b.y, 16);

        // --- write (V, 3*F): half 0 -> bins 0,2; half 1 -> bin 1 ---
        float* obase = out + (size_t)v * OUT_F + 4 * t;
        if (half_ == 0) {
            const float r0 = 1.0f / (s0 + EPSV);
            const float r2 = 1.0f / (s2 + EPSV);
            *reinterpret_cast<float4*>(obase) =
                make_float4(A0a.x * r0, A0a.y * r0, A0b.x * r0, A0b.y * r0);
            *reinterpret_cast<float4*>(obase + 2 * F_DIM) =
                make_float4(A2a.x * r2, A2a.y * r2, A2b.x * r2, A2b.y * r2);
        } else {
            const float r1 = 1.0f / (s1 + EPSV);
            *reinterpret_cast<float4*>(obase + F_DIM) =
                make_float4(A1a.x * r1, A1a.y * r1, A1b.x * r1, A1b.y * r1);
        }
    }
}

// ---------------------------------------------------------------- fallback (fp32 gather)
__global__ __launch_bounds__(256)
void softpixel_kernel_f(const float* __restrict__ features,
                        const float* __restrict__ distsq,
                        const int*   __restrict__ nidx,
                        const float* __restrict__ ls_ptr,
                        float*       __restrict__ out,
                        int V)
{
    const int lane   = threadIdx.x & 31;
    const int half_  = lane >> 4;
    const int t      = lane & 15;
    const int warp0  = (blockIdx.x * blockDim.x + threadIdx.x) >> 5;
    const int nwarps = (gridDim.x * blockDim.x) >> 5;

    const float ls     = __ldg(ls_ptr);
    const float scaler = 10.0f * ls * (float)SUBDIV;
    const float inv_ls = 1.0f / ls;

    for (int v = warp0; v < V; v += nwarps) {
        const float dsq    = __ldg(distsq + (size_t)v * K_NEIGH + lane);
        const int   my_idx = __ldg(nidx   + (size_t)v * K_NEIGH + lane);
        const float d  = sqrtf(dsq + EPSV);
        const float t1 = d - inv_ls;
        const float t2 = d - 2.0f * inv_ls;
        const float w0 = __expf(-scaler * d  * d);
        const float w1 = __expf(-scaler * t1 * t1);
        const float w2 = __expf(-scaler * t2 * t2);

        float s0 = w0, s1 = w1, s2 = w2;
        #pragma unroll
        for (int off = 16; off > 0; off >>= 1) {
            s0 += __shfl_xor_sync(FULLM, s0, off);
            s1 += __shfl_xor_sync(FULLM, s1, off);
            s2 += __shfl_xor_sync(FULLM, s2, off);
        }

        float4 a0 = make_float4(0.f, 0.f, 0.f, 0.f);
        float4 a1 = make_float4(0.f, 0.f, 0.f, 0.f);
        float4 a2 = make_float4(0.f, 0.f, 0.f, 0.f);
        const float* fbase = features + (size_t)4 * t;

        int kj = half_;
        #pragma unroll
        for (int j = 0; j < K_NEIGH / 2; ++j, kj += 2) {
            const int   ik = __shfl_sync(FULLM, my_idx, kj);
            const float b0 = __shfl_sync(FULLM, w0, kj);
            const float b1 = __shfl_sync(FULLM, w1, kj);
            const float b2 = __shfl_sync(FULLM, w2, kj);
            const float4 f = *reinterpret_cast<const float4*>(fbase + (size_t)ik * F_DIM);
            a0.x = fmaf(b0, f.x, a0.x); a0.y = fmaf(b0, f.y, a0.y);
            a0.z = fmaf(b0, f.z, a0.z); a0.w = fmaf(b0, f.w, a0.w);
            a1.x = fmaf(b1, f.x, a1.x); a1.y = fmaf(b1, f.y, a1.y);
            a1.z = fmaf(b1, f.z, a1.z); a1.w = fmaf(b1, f.w, a1.w);
            a2.x = fmaf(b2, f.x, a2.x); a2.y = fmaf(b2, f.y, a2.y);
            a2.z = fmaf(b2, f.z, a2.z); a2.w = fmaf(b2, f.w, a2.w);
        }

        a0.x += __shfl_xor_sync(FULLM, a0.x, 16); a0.y += __shfl_xor_sync(FULLM, a0.y, 16);
        a0.z += __shfl_xor_sync(FULLM, a0.z, 16); a0.w += __shfl_xor_sync(FULLM, a0.w, 16);
        a1.x += __shfl_xor_sync(FULLM, a1.x, 16); a1.y += __shfl_xor_sync(FULLM, a1.y, 16);
        a1.z += __shfl_xor_sync(FULLM, a1.z, 16); a1.w += __shfl_xor_sync(FULLM, a1.w, 16);
        a2.x += __shfl_xor_sync(FULLM, a2.x, 16); a2.y += __shfl_xor_sync(FULLM, a2.y, 16);
        a2.z += __shfl_xor_sync(FULLM, a2.z, 16); a2.w += __shfl_xor_sync(FULLM, a2.w, 16);

        float* obase = out + (size_t)v * OUT_F + 4 * t;
        if (half_ == 0) {
            const float r0 = 1.0f / (s0 + EPSV);
            const float r2 = 1.0f / (s2 + EPSV);
            *reinterpret_cast<float4*>(obase) =
                make_float4(a0.x * r0, a0.y * r0, a0.z * r0, a0.w * r0);
            *reinterpret_cast<float4*>(obase + 2 * F_DIM) =
                make_float4(a2.x * r2, a2.y * r2, a2.z * r2, a2.w * r2);
        } else {
            const float r1 = 1.0f / (s1 + EPSV);
            *reinterpret_cast<float4*>(obase + F_DIM) =
                make_float4(a1.x * r1, a1.y * r1, a1.z * r1, a1.w * r1);
        }
    }
}

extern "C" void kernel_launch(void* const* d_in, const int* in_sizes, int n_in,
                              void* d_out, int out_size)
{
    const float* features = (const float*)d_in[0];
    const float* distsq   = (const float*)d_in[1];
    const int*   nidx     = (const int*)  d_in[2];
    const float* ls       = (const float*)d_in[3];
    float*       out      = (float*)d_out;

    int V = out_size / OUT_F;
    if (V <= 0) V = in_sizes[1] / K_NEIGH;

    const int threads = 256;
    int blocks = (V * 32 + threads - 1) / threads;
    if (blocks < 1) blocks = 1;

    if (V <= V_CAP) {
        const int n4 = (V * F_DIM) / 4;               // float4 count
        int cblocks = (n4 + threads - 1) / threads;
        if (cblocks > 4096) cblocks = 4096;
        if (cblocks < 1) cblocks = 1;
        convert_kernel<<<cblocks, threads>>>(features, n4);
        softpixel_kernel_h<<<blocks, threads>>>(distsq, nidx, ls, out, V);
    } else {
        softpixel_kernel_f<<<blocks, threads>>>(features, distsq, nidx, ls, out, V);
    }
}

// round 17
// speedup vs baseline: 1.2737x; 1.1166x over previous
#include <cuda_runtime.h>
#include <cuda_fp16.h>
#include <cstdint>

// SoftPixelRadiusCNN:
//   d      = sqrt(distsq + EPS)
//   w_i(k) = exp(-scaler * (d_k - i/ls)^2),  scaler = 10*ls*SUBDIV
//   out[v, i*F + f] = sum_k w_i(k) * features[nidx[v,k], f] / (sum_k w_i(k) + EPS)
// V=100000, K=32, F=64, SUBDIV=3.
//
// R17 = R16 with the denominator reduction done via integer redux
// (__reduce_add_sync on 2^24 fixed-point weights: ~15 instrs vs 90-instr fp32
// butterfly; redux.f32 does not exist on this target).
//  - smem stage of pre-duplicated {(w0,w0),(w1,w1),(w2,w2),idx} uint4:
//    one broadcast LDS.128/iter replaces 3 SHFL + 2 PRMT
//  - HFMA2 datapath on fp16-compressed features (chain-8 drains, fp32 finish)

#define K_NEIGH 32
#define F_DIM   64
#define SUBDIV  3
#define EPSV    1e-6f
#define OUT_F   (SUBDIV * F_DIM)
#define FULLM   0xFFFFFFFFu
#define WARPS_PER_BLOCK 8

#define FIXP_SCALE     16777216.0f          // 2^24
#define FIXP_INV       (1.0f / 16777216.0f)

#define V_CAP   100352                       // static fp16 buffer capacity (rows)
__device__ __half g_feat16[(size_t)V_CAP * F_DIM];   // 12.85 MB module-static scratch

__device__ __forceinline__ __half2 u32_as_h2(uint32_t u) {
    __half2 h;
    *reinterpret_cast<uint32_t*>(&h) = u;
    return h;
}
__device__ __forceinline__ uint32_t h2_as_u32(__half2 h) {
    return *reinterpret_cast<uint32_t*>(&h);
}
// warp fp32 sum via integer redux on 2^24 fixed point (exact to ~6e-8/term;
// weights are in [0,1] and the sum of 32 fits far below 2^32)
__device__ __forceinline__ float warp_sum_fix(float w) {
    const unsigned q = (unsigned)(w * FIXP_SCALE);
    const unsigned s = __reduce_add_sync(FULLM, q);
    return (float)s * FIXP_INV;
}

// ---------------------------------------------------------------- convert
__global__ __launch_bounds__(256)
void convert_kernel(const float* __restrict__ features, int n4 /* V*F/4 */)
{
    const int stride = gridDim.x * blockDim.x;
    for (int i = blockIdx.x * blockDim.x + threadIdx.x; i < n4; i += stride) {
        const float4 x = reinterpret_cast<const float4*>(features)[i];
        __half2 lo = __floats2half2_rn(x.x, x.y);
        __half2 hi = __floats2half2_rn(x.z, x.w);
        reinterpret_cast<uint2*>(g_feat16)[i] = make_uint2(h2_as_u32(lo), h2_as_u32(hi));
    }
}

// ---------------------------------------------------------------- main
__global__ __launch_bounds__(256)
void softpixel_kernel_h(const float* __restrict__ distsq,
                        const int*   __restrict__ nidx,
                        const float* __restrict__ ls_ptr,
                        float*       __restrict__ out,
                        int V)
{
    __shared__ uint4 stage[WARPS_PER_BLOCK][K_NEIGH];

    const int lane   = threadIdx.x & 31;
    const int half_  = lane >> 4;      // 0 or 1
    const int t      = lane & 15;      // 4-col group within the half
    const int wib    = threadIdx.x >> 5;
    const int warp0  = (blockIdx.x * blockDim.x + threadIdx.x) >> 5;
    const int nwarps = (gridDim.x * blockDim.x) >> 5;

    const float ls     = __ldg(ls_ptr);
    const float scaler = 10.0f * ls * (float)SUBDIV;
    const float inv_ls = 1.0f / ls;

    const __half* fbase = g_feat16 + (size_t)4 * t;
    uint4* const mystage = stage[wib];

    for (int v = warp0; v < V; v += nwarps) {
        // --- per-lane neighbor (k = lane): distance, index, 3 bin weights ---
        const float dsq    = __ldg(distsq + (size_t)v * K_NEIGH + lane);
        const int   my_idx = __ldg(nidx   + (size_t)v * K_NEIGH + lane);
        const float d  = sqrtf(dsq + EPSV);
        const float t1 = d - inv_ls;
        const float t2 = d - 2.0f * inv_ls;
        const float w0 = __expf(-scaler * d  * d);
        const float w1 = __expf(-scaler * t1 * t1);
        const float w2 = __expf(-scaler * t2 * t2);

        // --- denominators via single-instruction integer redux ---
        const float s0 = warp_sum_fix(w0);
        const float s1 = warp_sum_fix(w1);
        const float s2 = warp_sum_fix(w2);

        // --- stage pre-duplicated weights + index: one STS.128 per lane ---
        const uint32_t u00 = h2_as_u32(__floats2half2_rn(w0, w0));
        const uint32_t u11 = h2_as_u32(__floats2half2_rn(w1, w1));
        const uint32_t u22 = h2_as_u32(__floats2half2_rn(w2, w2));
        __syncwarp();   // previous vertex's stage reads complete
        mystage[lane] = make_uint4(u00, u11, u22, (uint32_t)my_idx);
        __syncwarp();   // stage visible to whole warp

        // --- fp16 accumulators (drained to fp32 every 8 iterations) ---
        __half2 c0a = u32_as_h2(0), c0b = u32_as_h2(0);
        __half2 c1a = u32_as_h2(0), c1b = u32_as_h2(0);
        __half2 c2a = u32_as_h2(0), c2b = u32_as_h2(0);
        float2 A0a = make_float2(0.f,0.f), A0b = make_float2(0.f,0.f);
        float2 A1a = make_float2(0.f,0.f), A1b = make_float2(0.f,0.f);
        float2 A2a = make_float2(0.f,0.f), A2b = make_float2(0.f,0.f);

        int kj = half_;                    // this half's neighbors: half, half+2, ...
        #pragma unroll
        for (int j = 0; j < K_NEIGH / 2; ++j, kj += 2) {
            const uint4 q = mystage[kj];   // broadcast LDS.128 within each half
            const int   ik = (int)q.w;
            const uint2 p = *reinterpret_cast<const uint2*>(fbase + (size_t)ik * F_DIM);
            const __half2 fx  = u32_as_h2(p.x);   // cols 4t,4t+1
            const __half2 fy  = u32_as_h2(p.y);   // cols 4t+2,4t+3
            const __half2 b00 = u32_as_h2(q.x);
            const __half2 b11 = u32_as_h2(q.y);
            const __half2 b22 = u32_as_h2(q.z);
            c0a = __hfma2(b00, fx, c0a);  c0b = __hfma2(b00, fy, c0b);
            c1a = __hfma2(b11, fx, c1a);  c1b = __hfma2(b11, fy, c1b);
            c2a = __hfma2(b22, fx, c2a);  c2b = __hfma2(b22, fy, c2b);

            if (j == 7) {   // mid drain: keep fp16 chains at length 8
                float2 f2;
                f2 = __half22float2(c0a); A0a.x += f2.x; A0a.y += f2.y;
                f2 = __half22float2(c0b); A0b.x += f2.x; A0b.y += f2.y;
                f2 = __half22float2(c1a); A1a.x += f2.x; A1a.y += f2.y;
                f2 = __half22float2(c1b); A1b.x += f2.x; A1b.y += f2.y;
                f2 = __half22float2(c2a); A2a.x += f2.x; A2a.y += f2.y;
                f2 = __half22float2(c2b); A2b.x += f2.x; A2b.y += f2.y;
                c0a = u32_as_h2(0); c0b = u32_as_h2(0);
                c1a = u32_as_h2(0); c1b = u32_as_h2(0);
                c2a = u32_as_h2(0); c2b = u32_as_h2(0);
            }
        }
        {   // final drain
            float2 f2;
            f2 = __half22float2(c0a); A0a.x += f2.x; A0a.y += f2.y;
            f2 = __half22float2(c0b); A0b.x += f2.x; A0b.y += f2.y;
            f2 = __half22float2(c1a); A1a.x += f2.x; A1a.y += f2.y;
            f2 = __half22float2(c1b); A1b.x += f2.x; A1b.y += f2.y;
            f2 = __half22float2(c2a); A2a.x += f2.x; A2a.y += f2.y;
            f2 = __half22float2(c2b); A2b.x += f2.x; A2b.y += f2.y;
        }

        // --- combine even-k (half 0) / odd-k (half 1) partials: 12 SHFLs ---
        A0a.x += __shfl_xor_sync(FULLM, A0a.x, 16); A0a.y += __shfl_xor_sync(FULLM, A0a.y, 16);
        A0b.x += __shfl_xor_sync(FULLM, A0b.x, 16); A0b.y += __shfl_xor_sync(FULLM, A0b.y, 16);
        A1a.x += __shfl_xor_sync(FULLM, A1a.x, 16); A1a.y += __shfl_xor_sync(FULLM, A1a.y, 16);
        A1b.x += __shfl_xor_sync(FULLM, A1b.x, 16); A1b.y += __shfl_xor_sync(FULLM, A1b.y, 16);
        A2a.x += __shfl_xor_sync(FULLM, A2a.x, 16); A2a.y += __shfl_xor_sync(FULLM, A2a.y, 16);
        A2b.x += __shfl_xor_sync(FULLM, A2b.x, 16); A2b.y += __shfl_xor_sync(FULLM, A2b.y, 16);

        // --- write (V, 3*F): half 0 -> bins 0,2; half 1 -> bin 1 ---
        float* obase = out + (size_t)v * OUT_F + 4 * t;
        if (half_ == 0) {
            const float r0 = 1.0f / (s0 + EPSV);
            const float r2 = 1.0f / (s2 + EPSV);
            *reinterpret_cast<float4*>(obase) =
                make_float4(A0a.x * r0, A0a.y * r0, A0b.x * r0, A0b.y * r0);
            *reinterpret_cast<float4*>(obase + 2 * F_DIM) =
                make_float4(A2a.x * r2, A2a.y * r2, A2b.x * r2, A2b.y * r2);
        } else {
            const float r1 = 1.0f / (s1 + EPSV);
            *reinterpret_cast<float4*>(obase + F_DIM) =
                make_float4(A1a.x * r1, A1a.y * r1, A1b.x * r1, A1b.y * r1);
        }
    }
}

// ---------------------------------------------------------------- fallback (fp32 gather)
__global__ __launch_bounds__(256)
void softpixel_kernel_f(const float* __restrict__ features,
                        const float* __restrict__ distsq,
                        const int*   __restrict__ nidx,
                        const float* __restrict__ ls_ptr,
                        float*       __restrict__ out,
                        int V)
{
    const int lane   = threadIdx.x & 31;
    const int half_  = lane >> 4;
    const int t      = lane & 15;
    const int warp0  = (blockIdx.x * blockDim.x + threadIdx.x) >> 5;
    const int nwarps = (gridDim.x * blockDim.x) >> 5;

    const float ls     = __ldg(ls_ptr);
    const float scaler = 10.0f * ls * (float)SUBDIV;
    const float inv_ls = 1.0f / ls;

    for (int v = warp0; v < V; v += nwarps) {
        const float dsq    = __ldg(distsq + (size_t)v * K_NEIGH + lane);
        const int   my_idx = __ldg(nidx   + (size_t)v * K_NEIGH + lane);
        const float d  = sqrtf(dsq + EPSV);
        const float t1 = d - inv_ls;
        const float t2 = d - 2.0f * inv_ls;
        const float w0 = __expf(-scaler * d  * d);
        const float w1 = __expf(-scaler * t1 * t1);
        const float w2 = __expf(-scaler * t2 * t2);

        float s0 = w0, s1 = w1, s2 = w2;
        #pragma unroll
        for (int off = 16; off > 0; off >>= 1) {
            s0 += __shfl_xor_sync(FULLM, s0, off);
            s1 += __shfl_xor_sync(FULLM, s1, off);
            s2 += __shfl_xor_sync(FULLM, s2, off);
        }

        float4 a0 = make_float4(0.f, 0.f, 0.f, 0.f);
        float4 a1 = make_float4(0.f, 0.f, 0.f, 0.f);
        float4 a2 = make_float4(0.f, 0.f, 0.f, 0.f);
        const float* fbase = features + (size_t)4 * t;

        int kj = half_;
        #pragma unroll
        for (int j = 0; j < K_NEIGH / 2; ++j, kj += 2) {
            const int   ik = __shfl_sync(FULLM, my_idx, kj);
            const float b0 = __shfl_sync(FULLM, w0, kj);
            const float b1 = __shfl_sync(FULLM, w1, kj);
            const float b2 = __shfl_sync(FULLM, w2, kj);
            const float4 f = *reinterpret_cast<const float4*>(fbase + (size_t)ik * F_DIM);
            a0.x = fmaf(b0, f.x, a0.x); a0.y = fmaf(b0, f.y, a0.y);
            a0.z = fmaf(b0, f.z, a0.z); a0.w = fmaf(b0, f.w, a0.w);
            a1.x = fmaf(b1, f.x, a1.x); a1.y = fmaf(b1, f.y, a1.y);
            a1.z = fmaf(b1, f.z, a1.z); a1.w = fmaf(b1, f.w, a1.w);
            a2.x = fmaf(b2, f.x, a2.x); a2.y = fmaf(b2, f.y, a2.y);
            a2.z = fmaf(b2, f.z, a2.z); a2.w = fmaf(b2, f.w, a2.w);
        }

        a0.x += __shfl_xor_sync(FULLM, a0.x, 16); a0.y += __shfl_xor_sync(FULLM, a0.y, 16);
        a0.z += __shfl_xor_sync(FULLM, a0.z, 16); a0.w += __shfl_xor_sync(FULLM, a0.w, 16);
        a1.x += __shfl_xor_sync(FULLM, a1.x, 16); a1.y += __shfl_xor_sync(FULLM, a1.y, 16);
        a1.z += __shfl_xor_sync(FULLM, a1.z, 16); a1.w += __shfl_xor_sync(FULLM, a1.w, 16);
        a2.x += __shfl_xor_sync(FULLM, a2.x, 16); a2.y += __shfl_xor_sync(FULLM, a2.y, 16);
        a2.z += __shfl_xor_sync(FULLM, a2.z, 16); a2.w += __shfl_xor_sync(FULLM, a2.w, 16);

        float* obase = out + (size_t)v * OUT_F + 4 * t;
        if (half_ == 0) {
            const float r0 = 1.0f / (s0 + EPSV);
            const float r2 = 1.0f / (s2 + EPSV);
            *reinterpret_cast<float4*>(obase) =
                make_float4(a0.x * r0, a0.y * r0, a0.z * r0, a0.w * r0);
            *reinterpret_cast<float4*>(obase + 2 * F_DIM) =
                make_float4(a2.x * r2, a2.y * r2, a2.z * r2, a2.w * r2);
        } else {
            const float r1 = 1.0f / (s1 + EPSV);
            *reinterpret_cast<float4*>(obase + F_DIM) =
                make_float4(a1.x * r1, a1.y * r1, a1.z * r1, a1.w * r1);
        }
    }
}

extern "C" void kernel_launch(void* const* d_in, const int* in_sizes, int n_in,
                              void* d_out, int out_size)
{
    const float* features = (const float*)d_in[0];
    const float* distsq   = (const float*)d_in[1];
    const int*   nidx     = (const int*)  d_in[2];
    const float* ls       = (const float*)d_in[3];
    float*       out      = (float*)d_out;

    int V = out_size / OUT_F;
    if (V <= 0) V = in_sizes[1] / K_NEIGH;

    const int threads = 256;
    int blocks = (V * 32 + threads - 1) / threads;
    if (blocks < 1) blocks = 1;

    if (V <= V_CAP) {
        const int n4 = (V * F_DIM) / 4;               // float4 count
        int cblocks = (n4 + threads - 1) / threads;
        if (cblocks > 4096) cblocks = 4096;
        if (cblocks < 1) cblocks = 1;
        convert_kernel<<<cblocks, threads>>>(features, n4);
        softpixel_kernel_h<<<blocks, threads>>>(distsq, nidx, ls, out, V);
    } else {
        softpixel_kernel_f<<<blocks, threads>>>(features, distsq, nidx, ls, out, V);
    }
}